// round 7
// baseline (speedup 1.0000x reference)
#include <cuda_runtime.h>

constexpr int Lc = 2048;
constexpr int Ic = 32000;
constexpr int Dc = 256;
constexpr int NB = 148;          // <= SM count -> all blocks co-resident, barrier is safe
constexpr int NT = 256;
constexpr int NCHUNK = Ic / 64;  // 500 row-chunks of DE

// Scratch (device globals; no allocations allowed)
__device__ float g_part[2][NB][Dc];   // phase-A per-block GEMV partials
__device__ float g_w[Dc];             // final weighted row
__device__ unsigned g_count = 0;      // barrier arrival counter (self-resetting)
__device__ volatile unsigned g_gen = 0; // barrier generation (monotone across replays)

__device__ __forceinline__ void grid_barrier() {
    __syncthreads();
    if (threadIdx.x == 0) {
        __threadfence();                       // release this block's writes
        unsigned gen = g_gen;
        if (atomicAdd(&g_count, 1u) == NB - 1) {
            g_count = 0;                       // visible in L2 before gen bump (fence below)
            __threadfence();
            g_gen = gen + 1;                   // release
        } else {
            while (g_gen == gen) { }           // volatile spin (bypasses L1)
        }
        __threadfence();                       // acquire
    }
    __syncthreads();
}

__global__ void __launch_bounds__(NT) fused_kernel(
    const float* __restrict__ x,   const float* __restrict__ DE,
    const float* __restrict__ PE,  const float* __restrict__ D1w,
    const float* __restrict__ D2w, const float* __restrict__ Attw,
    float* __restrict__ out)
{
    __shared__ float sh[3072];   // reused: phase A x-rows | block0 chain | phase C w
    const int t = threadIdx.x;
    const int b = blockIdx.x;

    // ---------------- Phase A: dual GEMV p_k = x[L-2+k] @ DE ----------------
    {
        float* sx0 = sh;        // 64
        float* sx1 = sh + 64;   // 64
        const float* xr0 = x + (size_t)(Lc - 2) * Ic;
        const float* xr1 = x + (size_t)(Lc - 1) * Ic;
        float a0 = 0.f, a1 = 0.f;
        for (int c = b; c < NCHUNK; c += NB) {
            int r0 = c * 64;
            __syncthreads();
            if (t < 64)       sx0[t]      = xr0[r0 + t];
            else if (t < 128) sx1[t - 64] = xr1[r0 + t - 64];
            __syncthreads();
            const float* de = DE + (size_t)r0 * Dc + t;
            #pragma unroll
            for (int r = 0; r < 64; ++r) {
                float v = de[(size_t)r * Dc];
                a0 = fmaf(sx0[r], v, a0);
                a1 = fmaf(sx1[r], v, a1);
            }
        }
        g_part[0][b][t] = a0;
        g_part[1][b][t] = a1;
    }

    // Prefetch D1 + Att into L2 (1 MB total, one float4 per thread)
    {
        float s = 0.f;
        int idx = b * NT + t;
        if (idx < (2 * Dc * Dc) / 4) {       // 32768 float4 each
            float4 v = __ldcg((const float4*)D1w  + idx);
            float4 u = __ldcg((const float4*)Attw + idx);
            s += v.x + v.y + v.z + v.w + u.x + u.y + u.z + u.w;
        }
        asm volatile("" :: "f"(s));          // keep the loads
    }

    grid_barrier();   // g_part complete everywhere

    // ------- Phase B: block 0 runs the small chain; others prefetch D2 -------
    if (b == 0) {
        const float inv1 = 1.0f / (float)(Lc - 1);
        const float inv2 = 1.0f / (float)Lc;

        // p-reduce (+ PE bias)
        float p0 = PE[(size_t)(Lc - 2) * Dc + t];
        float p1 = PE[(size_t)(Lc - 1) * Dc + t];
        #pragma unroll 4
        for (int i = 0; i < NB; ++i) {
            p0 += g_part[0][i][t];
            p1 += g_part[1][i][t];
        }

        float* sc0 = sh;            // 512: concat row input, row L-2
        float* sc1 = sh + 512;      // 512: row L-1
        float* sp0 = sh + 1024;     // [4][256] k-split partials, row L-2
        float* sp1 = sh + 2048;     // [4][256] row L-1
        sc0[t] = p0;  sc0[Dc + t] = (p0 + p1) * inv1;   // pool1 rows
        sc1[t] = p1;  sc1[Dc + t] = p1 * inv2;
        __syncthreads();

        const int kk = t >> 6;      // k-phase 0..3
        const int cg = t & 63;      // column group (4 cols)

        // dense1 = concat(p, pool1) @ D1   (float4 over columns, k-split by 4)
        float d00=0,d01=0,d02=0,d03=0, d10=0,d11=0,d12=0,d13=0;
        #pragma unroll 8
        for (int k = kk; k < 2 * Dc; k += 4) {
            float4 v = *(const float4*)(D1w + (size_t)k * Dc + cg * 4);
            float c0 = sc0[k], c1 = sc1[k];
            d00 = fmaf(c0, v.x, d00); d01 = fmaf(c0, v.y, d01);
            d02 = fmaf(c0, v.z, d02); d03 = fmaf(c0, v.w, d03);
            d10 = fmaf(c1, v.x, d10); d11 = fmaf(c1, v.y, d11);
            d12 = fmaf(c1, v.z, d12); d13 = fmaf(c1, v.w, d13);
        }
        sp0[kk * Dc + cg * 4 + 0] = d00; sp0[kk * Dc + cg * 4 + 1] = d01;
        sp0[kk * Dc + cg * 4 + 2] = d02; sp0[kk * Dc + cg * 4 + 3] = d03;
        sp1[kk * Dc + cg * 4 + 0] = d10; sp1[kk * Dc + cg * 4 + 1] = d11;
        sp1[kk * Dc + cg * 4 + 2] = d12; sp1[kk * Dc + cg * 4 + 3] = d13;
        __syncthreads();
        float d0f = sp0[t] + sp0[Dc + t] + sp0[2 * Dc + t] + sp0[3 * Dc + t];
        float d1f = sp1[t] + sp1[Dc + t] + sp1[2 * Dc + t] + sp1[3 * Dc + t];
        __syncthreads();

        // attention = concat(dense1, pool2) @ Att
        sc0[t] = d0f;  sc0[Dc + t] = (d0f + d1f) * inv1;
        sc1[t] = d1f;  sc1[Dc + t] = d1f * inv2;
        __syncthreads();

        float a00=0,a01=0,a02=0,a03=0, a10=0,a11=0,a12=0,a13=0;
        #pragma unroll 8
        for (int k = kk; k < 2 * Dc; k += 4) {
            float4 v = *(const float4*)(Attw + (size_t)k * Dc + cg * 4);
            float c0 = sc0[k], c1 = sc1[k];
            a00 = fmaf(c0, v.x, a00); a01 = fmaf(c0, v.y, a01);
            a02 = fmaf(c0, v.z, a02); a03 = fmaf(c0, v.w, a03);
            a10 = fmaf(c1, v.x, a10); a11 = fmaf(c1, v.y, a11);
            a12 = fmaf(c1, v.z, a12); a13 = fmaf(c1, v.w, a13);
        }
        sp0[kk * Dc + cg * 4 + 0] = a00; sp0[kk * Dc + cg * 4 + 1] = a01;
        sp0[kk * Dc + cg * 4 + 2] = a02; sp0[kk * Dc + cg * 4 + 3] = a03;
        sp1[kk * Dc + cg * 4 + 0] = a10; sp1[kk * Dc + cg * 4 + 1] = a11;
        sp1[kk * Dc + cg * 4 + 2] = a12; sp1[kk * Dc + cg * 4 + 3] = a13;
        __syncthreads();
        float a0f = sp0[t] + sp0[Dc + t] + sp0[2 * Dc + t] + sp0[3 * Dc + t];
        float a1f = sp1[t] + sp1[Dc + t] + sp1[2 * Dc + t] + sp1[3 * Dc + t];

        // w = d0*a0 + d1*a1  (SA.T sum of the two surviving weighted rows)
        g_w[t] = d0f * a0f + d1f * a1f;
    } else {
        // Blocks 1..147: pull D2 (32.8 MB) into L2 while block 0 computes
        float s = 0.f;
        const float4* d2v = (const float4*)D2w;
        for (int idx = (b - 1) * NT + t; idx < (Dc * Ic) / 4; idx += (NB - 1) * NT) {
            float4 v = __ldcg(d2v + idx);
            s += v.x + v.y + v.z + v.w;
        }
        asm volatile("" :: "f"(s));
    }

    grid_barrier();   // g_w ready, D2 hot in L2

    // ---------------- Phase C: out = w @ D2 (L2-resident) ----------------
    {
        float* sw = sh;
        sw[t] = g_w[t];
        __syncthreads();
        for (int c = b; c < Ic / NT; c += NB) {   // 125 chunks of 256 cols
            int i = c * NT + t;
            const float* d2 = D2w + i;
            float acc = 0.f;
            #pragma unroll 16
            for (int d = 0; d < Dc; ++d)
                acc = fmaf(sw[d], d2[(size_t)d * Ic], acc);
            out[i] = acc;
        }
    }
}

extern "C" void kernel_launch(void* const* d_in, const int* in_sizes, int n_in,
                              void* d_out, int out_size) {
    const float* x   = (const float*)d_in[0];  // [L, I]
    const float* DE  = (const float*)d_in[1];  // [I, D]
    const float* PE  = (const float*)d_in[2];  // [L, D]
    const float* D1w = (const float*)d_in[3];  // [2D, D]
    const float* D2w = (const float*)d_in[4];  // [D, I]
    const float* Att = (const float*)d_in[5];  // [2D, D]
    float* out = (float*)d_out;                // [1, I]
    (void)in_sizes; (void)n_in; (void)out_size;

    fused_kernel<<<NB, NT>>>(x, DE, PE, D1w, D2w, Att, out);
}

// round 8
// speedup vs baseline: 1.5219x; 1.5219x over previous
#include <cuda_runtime.h>

constexpr int Lc = 2048;
constexpr int Ic = 32000;
constexpr int Dc = 256;
constexpr int NB = 148;          // 1 CTA/SM -> all co-resident, grid barrier safe
constexpr int NT = 1024;         // 32 warps/SM: the R7 fusion died at 8 warps/SM
constexpr int NCHUNK = Ic / 256; // 125 row-chunks of DE, <= NB (one per block)

// Scratch (device globals; no allocation allowed)
__device__ float g_part[2][NCHUNK][Dc]; // phase-A per-block GEMV partials
__device__ float g_w[Dc];               // final weighted row
__device__ unsigned g_count = 0;        // barrier arrivals (self-resetting)
__device__ volatile unsigned g_gen = 0; // barrier generation (monotone across replays)

__device__ __forceinline__ void grid_barrier() {
    __syncthreads();
    if (threadIdx.x == 0) {
        __threadfence();                       // release
        unsigned gen = g_gen;
        if (atomicAdd(&g_count, 1u) == NB - 1) {
            g_count = 0;
            __threadfence();
            g_gen = gen + 1;                   // release
        } else {
            while (g_gen == gen) { }
        }
        __threadfence();                       // acquire
    }
    __syncthreads();
}

__global__ void __launch_bounds__(NT) fused_kernel(
    const float* __restrict__ x,   const float* __restrict__ DE,
    const float* __restrict__ PE,  const float* __restrict__ D1w,
    const float* __restrict__ D2w, const float* __restrict__ Attw,
    float* __restrict__ out)
{
    // Reused layout:
    //  A: sx0[256] sx1[256] | red0[1024] red1[1024]      (at 0 / 256 / 512 / 1536)
    //  B: sc0[512] sc1[512] | sp0[4096] sp1[4096]        (at 0 / 512 / 1024 / 5120)
    //  C: sw[256]           | red[1024]                  (at 0 / 1024)
    __shared__ float sh[9216];
    const int t   = threadIdx.x;
    const int b   = blockIdx.x;
    const int col = t & 255;
    const int q   = t >> 8;       // 0..3

    // ================= Phase A: p_k = x[L-2+k] @ DE (dual GEMV) =================
    if (b < NCHUNK) {
        float* sx0  = sh;
        float* sx1  = sh + 256;
        float* red0 = sh + 512;
        float* red1 = sh + 1536;
        const int r0 = b * 256;
        if (t < 256)      sx0[t]       = x[(size_t)(Lc - 2) * Ic + r0 + t];
        else if (t < 512) sx1[t - 256] = x[(size_t)(Lc - 1) * Ic + r0 + t - 256];
        __syncthreads();

        const float* de = DE + (size_t)(r0 + q * 64) * Dc + col;
        const float* xs0 = sx0 + q * 64;
        const float* xs1 = sx1 + q * 64;
        float a0 = 0.f, a1 = 0.f;
        #pragma unroll 16
        for (int r = 0; r < 64; ++r) {
            float v = de[(size_t)r * Dc];
            a0 = fmaf(xs0[r], v, a0);
            a1 = fmaf(xs1[r], v, a1);
        }
        red0[q * 256 + col] = a0;
        red1[q * 256 + col] = a1;
        __syncthreads();
        if (t < 256) {
            g_part[0][b][t] = red0[t] + red0[256 + t] + red0[512 + t] + red0[768 + t];
            g_part[1][b][t] = red1[t] + red1[256 + t] + red1[512 + t] + red1[768 + t];
        }
    }

    // Warm D1 + Att into L2 (1 MB total; first 32 blocks, one float4 pair each)
    {
        int idx = b * NT + t;
        if (idx < (2 * Dc * Dc) / 4) {
            float4 v = __ldcg((const float4*)D1w  + idx);
            float4 u = __ldcg((const float4*)Attw + idx);
            float s = v.x + v.y + v.z + v.w + u.x + u.y + u.z + u.w;
            asm volatile("" :: "f"(s));
        }
    }

    grid_barrier();   // g_part complete everywhere; D1/Att in L2

    // ===== Phase B: block 0 runs the serial chain; blocks 1..147 pull D2 to L2 =====
    if (b == 0) {
        const float inv1 = 1.0f / (float)(Lc - 1);
        const float inv2 = 1.0f / (float)Lc;
        float* sc0 = sh;
        float* sc1 = sh + 512;
        float* sp0 = sh + 1024;   // [16][256]
        float* sp1 = sh + 5120;   // [16][256]

        // --- p-reduce over 125 chunk-partials (4-way split), + PE bias ---
        {
            float r0s = 0.f, r1s = 0.f;
            for (int i = q; i < NCHUNK; i += 4) {
                r0s += g_part[0][i][col];
                r1s += g_part[1][i][col];
            }
            sp0[q * 256 + col] = r0s;
            sp1[q * 256 + col] = r1s;
            __syncthreads();
            if (t < 256) {
                float p0 = PE[(size_t)(Lc - 2) * Dc + t]
                         + sp0[t] + sp0[256 + t] + sp0[512 + t] + sp0[768 + t];
                float p1 = PE[(size_t)(Lc - 1) * Dc + t]
                         + sp1[t] + sp1[256 + t] + sp1[512 + t] + sp1[768 + t];
                sc0[t] = p0;  sc0[Dc + t] = (p0 + p1) * inv1;   // pool1 rows
                sc1[t] = p1;  sc1[Dc + t] = p1 * inv2;
            }
            __syncthreads();
        }

        const int kk = t >> 6;    // 0..15 (16-way k-split)
        const int cg = t & 63;    // 4 columns each (float4)
        float d0f = 0.f, d1f = 0.f;

        // --- dense1 = concat(p, pool1) @ D1 ---
        {
            float d00=0,d01=0,d02=0,d03=0, d10=0,d11=0,d12=0,d13=0;
            #pragma unroll 8
            for (int k = kk; k < 2 * Dc; k += 16) {
                float4 v = *(const float4*)(D1w + (size_t)k * Dc + cg * 4);
                float c0 = sc0[k], c1 = sc1[k];
                d00 = fmaf(c0, v.x, d00); d01 = fmaf(c0, v.y, d01);
                d02 = fmaf(c0, v.z, d02); d03 = fmaf(c0, v.w, d03);
                d10 = fmaf(c1, v.x, d10); d11 = fmaf(c1, v.y, d11);
                d12 = fmaf(c1, v.z, d12); d13 = fmaf(c1, v.w, d13);
            }
            sp0[kk * 256 + cg * 4 + 0] = d00; sp0[kk * 256 + cg * 4 + 1] = d01;
            sp0[kk * 256 + cg * 4 + 2] = d02; sp0[kk * 256 + cg * 4 + 3] = d03;
            sp1[kk * 256 + cg * 4 + 0] = d10; sp1[kk * 256 + cg * 4 + 1] = d11;
            sp1[kk * 256 + cg * 4 + 2] = d12; sp1[kk * 256 + cg * 4 + 3] = d13;
            __syncthreads();
            if (t < 256) {
                #pragma unroll
                for (int j = 0; j < 16; ++j) {
                    d0f += sp0[j * 256 + t];
                    d1f += sp1[j * 256 + t];
                }
                sc0[t] = d0f;  sc0[Dc + t] = (d0f + d1f) * inv1;  // pool2 rows
                sc1[t] = d1f;  sc1[Dc + t] = d1f * inv2;
            }
            __syncthreads();
        }

        // --- attention = concat(dense1, pool2) @ Att ---
        {
            float a00=0,a01=0,a02=0,a03=0, a10=0,a11=0,a12=0,a13=0;
            #pragma unroll 8
            for (int k = kk; k < 2 * Dc; k += 16) {
                float4 v = *(const float4*)(Attw + (size_t)k * Dc + cg * 4);
                float c0 = sc0[k], c1 = sc1[k];
                a00 = fmaf(c0, v.x, a00); a01 = fmaf(c0, v.y, a01);
                a02 = fmaf(c0, v.z, a02); a03 = fmaf(c0, v.w, a03);
                a10 = fmaf(c1, v.x, a10); a11 = fmaf(c1, v.y, a11);
                a12 = fmaf(c1, v.z, a12); a13 = fmaf(c1, v.w, a13);
            }
            sp0[kk * 256 + cg * 4 + 0] = a00; sp0[kk * 256 + cg * 4 + 1] = a01;
            sp0[kk * 256 + cg * 4 + 2] = a02; sp0[kk * 256 + cg * 4 + 3] = a03;
            sp1[kk * 256 + cg * 4 + 0] = a10; sp1[kk * 256 + cg * 4 + 1] = a11;
            sp1[kk * 256 + cg * 4 + 2] = a12; sp1[kk * 256 + cg * 4 + 3] = a13;
            __syncthreads();
            if (t < 256) {
                float a0f = 0.f, a1f = 0.f;
                #pragma unroll
                for (int j = 0; j < 16; ++j) {
                    a0f += sp0[j * 256 + t];
                    a1f += sp1[j * 256 + t];
                }
                // w = d0*a0 + d1*a1 (SA.T sum of the two surviving weighted rows)
                g_w[t] = d0f * a0f + d1f * a1f;
            }
        }
    } else {
        // Blocks 1..147: pull D2 (32.8 MB) into L2 behind block 0's serial window
        const float4* d2v = (const float4*)D2w;
        const int total = (Dc * Ic) / 4;          // 2,048,000 float4
        float s = 0.f;
        #pragma unroll 4
        for (int idx = (b - 1) * NT + t; idx < total; idx += (NB - 1) * NT) {
            float4 v = __ldcg(d2v + idx);
            s += v.x + v.y + v.z + v.w;
        }
        asm volatile("" :: "f"(s));
    }

    grid_barrier();   // g_w ready; D2 hot in L2

    // ================= Phase C: out = w @ D2 (L2-resident) =================
    if (b < NCHUNK) {   // 125 chunks of 256 output columns, one per block
        float* sw  = sh;
        float* red = sh + 1024;
        if (t < 256) sw[t] = g_w[t];
        __syncthreads();
        const int i = b * 256 + col;
        const float* d2 = D2w + (size_t)(q * 64) * Ic + i;
        const float* swq = sw + q * 64;
        float acc = 0.f;
        #pragma unroll 16
        for (int d = 0; d < 64; ++d)
            acc = fmaf(swq[d], d2[(size_t)d * Ic], acc);
        red[q * 256 + col] = acc;
        __syncthreads();
        if (t < 256)
            out[b * 256 + t] = red[t] + red[256 + t] + red[512 + t] + red[768 + t];
    }
}

extern "C" void kernel_launch(void* const* d_in, const int* in_sizes, int n_in,
                              void* d_out, int out_size) {
    const float* x   = (const float*)d_in[0];  // [L, I]
    const float* DE  = (const float*)d_in[1];  // [I, D]
    const float* PE  = (const float*)d_in[2];  // [L, D]
    const float* D1w = (const float*)d_in[3];  // [2D, D]
    const float* D2w = (const float*)d_in[4];  // [D, I]
    const float* Att = (const float*)d_in[5];  // [2D, D]
    float* out = (float*)d_out;                // [1, I]
    (void)in_sizes; (void)n_in; (void)out_size;

    fused_kernel<<<NB, NT>>>(x, DE, PE, D1w, D2w, Att, out);
}

// round 9
// speedup vs baseline: 1.9231x; 1.2636x over previous
#include <cuda_runtime.h>

constexpr int Lc = 2048;
constexpr int Ic = 32000;
constexpr int Dc = 256;

// kernel A: dual GEMV over DE, per-block partials (no atomics, no init kernel)
constexpr int KA_NB = 250;          // 128 DE rows per block
constexpr int KA_NT = 1024;
// kernel B: 1 chain block + 147 D2-prefetch blocks (kernel end = join)
constexpr int KB_NB = 148;
constexpr int KB_NT = 1024;
// kernel C: out = w @ D2 (L2-resident)
constexpr int KC_NB = 250;          // 128 output cols per block
constexpr int KC_NT = 512;

// Scratch (device globals; allocation is forbidden)
__device__ float g_part[2][KA_NB][Dc];
__device__ float g_w[Dc];

// ============ kA: p_k partials = x[L-2+k] @ DE (row-chunked) ============
// Block b owns DE rows [128b, 128b+128). 4-way row split, shared reduce.
// Also warms D1+Att (1 MB) into L2 for kB's chain.
__global__ void __launch_bounds__(KA_NT) kA_posembed(
    const float* __restrict__ x,  const float* __restrict__ DE,
    const float* __restrict__ D1w, const float* __restrict__ Attw)
{
    __shared__ float sx0[128], sx1[128], red0[1024], red1[1024];
    const int t = threadIdx.x, b = blockIdx.x;
    const int col = t & 255, q = t >> 8;        // q: 0..3 (32 rows each)
    const int r0 = b * 128;

    if (t < 128)      sx0[t]       = x[(size_t)(Lc - 2) * Ic + r0 + t];
    else if (t < 256) sx1[t - 128] = x[(size_t)(Lc - 1) * Ic + r0 + t - 128];
    __syncthreads();

    const float* de  = DE + (size_t)(r0 + q * 32) * Dc + col;
    const float* xs0 = sx0 + q * 32;
    const float* xs1 = sx1 + q * 32;
    float a0 = 0.f, a1 = 0.f;
    #pragma unroll
    for (int r = 0; r < 32; ++r) {
        float v = de[(size_t)r * Dc];
        a0 = fmaf(xs0[r], v, a0);
        a1 = fmaf(xs1[r], v, a1);
    }
    red0[q * 256 + col] = a0;
    red1[q * 256 + col] = a1;
    __syncthreads();
    if (t < 256) {
        g_part[0][b][t] = red0[t] + red0[256 + t] + red0[512 + t] + red0[768 + t];
        g_part[1][b][t] = red1[t] + red1[256 + t] + red1[512 + t] + red1[768 + t];
    }

    // Warm D1 + Att into L2 (2 * 64K floats = 32768 float4 pairs)
    int idx = b * KA_NT + t;
    if (idx < (2 * Dc * Dc) / 4) {
        float4 v = __ldcg((const float4*)D1w  + idx);
        float4 u = __ldcg((const float4*)Attw + idx);
        float s = v.x + v.y + v.z + v.w + u.x + u.y + u.z + u.w;
        asm volatile("" :: "f"(s));
    }
}

// ==== kB: block 0 = serial chain; blocks 1..147 = D2 -> L2 prefetch ====
__global__ void __launch_bounds__(KB_NT) kB_chain(
    const float* __restrict__ PE,  const float* __restrict__ D1w,
    const float* __restrict__ Attw, const float* __restrict__ D2w)
{
    const int t = threadIdx.x, b = blockIdx.x;

    if (b != 0) {
        // Pull D2 (32.8 MB) into L2 behind block 0's serial chain.
        const float4* d2v = (const float4*)D2w;
        const int total = (Dc * Ic) / 4;              // 2,048,000 float4
        float s = 0.f;
        #pragma unroll 4
        for (int idx = (b - 1) * KB_NT + t; idx < total; idx += (KB_NB - 1) * KB_NT) {
            float4 v = __ldcg(d2v + idx);
            s += v.x + v.y + v.z + v.w;
        }
        asm volatile("" :: "f"(s));
        return;
    }

    // ---------------- block 0: full small chain ----------------
    __shared__ float sc0[512], sc1[512], sp0[4096], sp1[4096];
    const float inv1 = 1.0f / (float)(Lc - 1);
    const float inv2 = 1.0f / (float)Lc;
    const int col = t & 255, q = t >> 8;

    // p-reduce over 250 block-partials (4-way split) + PE bias
    {
        float r0s = 0.f, r1s = 0.f;
        #pragma unroll 8
        for (int i = q; i < KA_NB; i += 4) {
            r0s += g_part[0][i][col];
            r1s += g_part[1][i][col];
        }
        sp0[q * 256 + col] = r0s;
        sp1[q * 256 + col] = r1s;
        __syncthreads();
        if (t < 256) {
            float p0 = PE[(size_t)(Lc - 2) * Dc + t]
                     + sp0[t] + sp0[256 + t] + sp0[512 + t] + sp0[768 + t];
            float p1 = PE[(size_t)(Lc - 1) * Dc + t]
                     + sp1[t] + sp1[256 + t] + sp1[512 + t] + sp1[768 + t];
            sc0[t] = p0;  sc0[Dc + t] = (p0 + p1) * inv1;   // pool1 rows
            sc1[t] = p1;  sc1[Dc + t] = p1 * inv2;
        }
        __syncthreads();
    }

    const int kk = t >> 6;    // 16-way k-split over the 512-long concat dim
    const int cg = t & 63;    // 4 columns each (float4)
    float d0f = 0.f, d1f = 0.f;

    // dense1 = concat(p, pool1) @ D1
    {
        float d00=0,d01=0,d02=0,d03=0, d10=0,d11=0,d12=0,d13=0;
        #pragma unroll 8
        for (int k = kk; k < 2 * Dc; k += 16) {
            float4 v = *(const float4*)(D1w + (size_t)k * Dc + cg * 4);
            float c0 = sc0[k], c1 = sc1[k];
            d00 = fmaf(c0, v.x, d00); d01 = fmaf(c0, v.y, d01);
            d02 = fmaf(c0, v.z, d02); d03 = fmaf(c0, v.w, d03);
            d10 = fmaf(c1, v.x, d10); d11 = fmaf(c1, v.y, d11);
            d12 = fmaf(c1, v.z, d12); d13 = fmaf(c1, v.w, d13);
        }
        int o = kk * 256 + cg * 4;
        sp0[o+0]=d00; sp0[o+1]=d01; sp0[o+2]=d02; sp0[o+3]=d03;
        sp1[o+0]=d10; sp1[o+1]=d11; sp1[o+2]=d12; sp1[o+3]=d13;
        __syncthreads();
        if (t < 256) {
            #pragma unroll
            for (int j = 0; j < 16; ++j) { d0f += sp0[j*256+t]; d1f += sp1[j*256+t]; }
            sc0[t] = d0f;  sc0[Dc + t] = (d0f + d1f) * inv1;  // pool2 rows
            sc1[t] = d1f;  sc1[Dc + t] = d1f * inv2;
        }
        __syncthreads();
    }

    // attention = concat(dense1, pool2) @ Att;  w = d0*a0 + d1*a1
    {
        float a00=0,a01=0,a02=0,a03=0, a10=0,a11=0,a12=0,a13=0;
        #pragma unroll 8
        for (int k = kk; k < 2 * Dc; k += 16) {
            float4 v = *(const float4*)(Attw + (size_t)k * Dc + cg * 4);
            float c0 = sc0[k], c1 = sc1[k];
            a00 = fmaf(c0, v.x, a00); a01 = fmaf(c0, v.y, a01);
            a02 = fmaf(c0, v.z, a02); a03 = fmaf(c0, v.w, a03);
            a10 = fmaf(c1, v.x, a10); a11 = fmaf(c1, v.y, a11);
            a12 = fmaf(c1, v.z, a12); a13 = fmaf(c1, v.w, a13);
        }
        int o = kk * 256 + cg * 4;
        sp0[o+0]=a00; sp0[o+1]=a01; sp0[o+2]=a02; sp0[o+3]=a03;
        sp1[o+0]=a10; sp1[o+1]=a11; sp1[o+2]=a12; sp1[o+3]=a13;
        __syncthreads();
        if (t < 256) {
            float a0f = 0.f, a1f = 0.f;
            #pragma unroll
            for (int j = 0; j < 16; ++j) { a0f += sp0[j*256+t]; a1f += sp1[j*256+t]; }
            g_w[t] = d0f * a0f + d1f * a1f;   // SA.T sum of the 2 surviving rows
        }
    }
}

// ============ kC: out[i] = sum_d w[d] * D2[d][i]  (D2 hot in L2) ============
// Block b owns cols [128b, 128b+128). 4-way d-split, shared reduce.
__global__ void __launch_bounds__(KC_NT) kC_out(
    const float* __restrict__ D2w, float* __restrict__ out)
{
    __shared__ float sw[Dc], red[512];
    const int t = threadIdx.x, b = blockIdx.x;
    const int c = t & 127, dg = t >> 7;      // dg: 0..3 (64 d's each)
    if (t < Dc) sw[t] = g_w[t];
    __syncthreads();

    const int i = b * 128 + c;
    const float* d2 = D2w + (size_t)(dg * 64) * Ic + i;
    const float* swq = sw + dg * 64;
    float acc = 0.f;
    #pragma unroll 16
    for (int d = 0; d < 64; ++d)
        acc = fmaf(swq[d], d2[(size_t)d * Ic], acc);
    red[dg * 128 + c] = acc;
    __syncthreads();
    if (t < 128)
        out[b * 128 + t] = red[t] + red[128 + t] + red[256 + t] + red[384 + t];
}

extern "C" void kernel_launch(void* const* d_in, const int* in_sizes, int n_in,
                              void* d_out, int out_size) {
    const float* x   = (const float*)d_in[0];  // [L, I]
    const float* DE  = (const float*)d_in[1];  // [I, D]
    const float* PE  = (const float*)d_in[2];  // [L, D]
    const float* D1w = (const float*)d_in[3];  // [2D, D]
    const float* D2w = (const float*)d_in[4];  // [D, I]
    const float* Att = (const float*)d_in[5];  // [2D, D]
    float* out = (float*)d_out;                // [1, I]
    (void)in_sizes; (void)n_in; (void)out_size;

    kA_posembed<<<KA_NB, KA_NT>>>(x, DE, D1w, Att);
    kB_chain<<<KB_NB, KB_NT>>>(PE, D1w, Att, D2w);
    kC_out<<<KC_NB, KC_NT>>>(D2w, out);
}

// round 10
// speedup vs baseline: 2.0403x; 1.0609x over previous
#include <cuda_runtime.h>

constexpr int Lc = 2048;
constexpr int Ic = 32000;
constexpr int Dc = 256;
constexpr int NB = 148;           // = SM count; kBC needs co-residency for the flag
constexpr int NT = 1024;
constexpr int NCHUNK_A = Ic / 32;   // 1000 chunks of 32 DE rows
constexpr int NCHUNK_C = Ic / 128;  // 250 chunks of 128 out cols

// Scratch (device globals; allocation is forbidden)
__device__ float g_part[2][NB][Dc];
__device__ float g_w[Dc];
__device__ volatile unsigned g_flag;   // reset by kA each launch, raised by kBC block 0

// ================= kA: dual GEMV p_k = x[L-2+k] @ DE =================
// Thread (rg, cg): rg = t>>6 owns 2 rows per chunk, cg = t&63 owns 4 cols.
// Warp = 32 consecutive cg at fixed rg -> 512B coalesced float4 loads of DE;
// x loads are warp-uniform scalars (1 request, L1 broadcast). No smem in loop.
__global__ void __launch_bounds__(NT) kA_posembed(
    const float* __restrict__ x,   const float* __restrict__ DE,
    const float* __restrict__ D1w, const float* __restrict__ Attw)
{
    const int t = threadIdx.x, b = blockIdx.x;
    const int rg = t >> 6, cg = t & 63;

    if (b == 0 && t == 0) g_flag = 0;   // replay-safe reset for kBC's one-way flag

    const float* xr0 = x + (size_t)(Lc - 2) * Ic;
    const float* xr1 = x + (size_t)(Lc - 1) * Ic;

    float4 a0 = make_float4(0.f, 0.f, 0.f, 0.f);
    float4 a1 = make_float4(0.f, 0.f, 0.f, 0.f);

    for (int c = b; c < NCHUNK_A; c += NB) {
        const int r = c * 32 + rg * 2;
        const float x00 = __ldg(xr0 + r), x01 = __ldg(xr0 + r + 1);
        const float x10 = __ldg(xr1 + r), x11 = __ldg(xr1 + r + 1);
        const float4 v0 = *(const float4*)(DE + (size_t)r       * Dc + cg * 4);
        const float4 v1 = *(const float4*)(DE + (size_t)(r + 1) * Dc + cg * 4);
        a0.x = fmaf(x00, v0.x, a0.x); a0.y = fmaf(x00, v0.y, a0.y);
        a0.z = fmaf(x00, v0.z, a0.z); a0.w = fmaf(x00, v0.w, a0.w);
        a0.x = fmaf(x01, v1.x, a0.x); a0.y = fmaf(x01, v1.y, a0.y);
        a0.z = fmaf(x01, v1.z, a0.z); a0.w = fmaf(x01, v1.w, a0.w);
        a1.x = fmaf(x10, v0.x, a1.x); a1.y = fmaf(x10, v0.y, a1.y);
        a1.z = fmaf(x10, v0.z, a1.z); a1.w = fmaf(x10, v0.w, a1.w);
        a1.x = fmaf(x11, v1.x, a1.x); a1.y = fmaf(x11, v1.y, a1.y);
        a1.z = fmaf(x11, v1.z, a1.z); a1.w = fmaf(x11, v1.w, a1.w);
    }

    __shared__ float red0[16 * 256], red1[16 * 256];
    *(float4*)(red0 + rg * 256 + cg * 4) = a0;
    *(float4*)(red1 + rg * 256 + cg * 4) = a1;
    __syncthreads();
    if (t < 256) {
        float s0 = 0.f, s1 = 0.f;
        #pragma unroll
        for (int j = 0; j < 16; ++j) {
            s0 += red0[j * 256 + t];
            s1 += red1[j * 256 + t];
        }
        g_part[0][b][t] = s0;
        g_part[1][b][t] = s1;
    }

    // Warm D1 + Att (1 MB) into L2 for kBC's chain
    const int idx = b * NT + t;
    if (idx < (2 * Dc * Dc) / 4) {
        float4 v = __ldcg((const float4*)D1w  + idx);
        float4 u = __ldcg((const float4*)Attw + idx);
        float s = v.x + v.y + v.z + v.w + u.x + u.y + u.z + u.w;
        asm volatile("" :: "f"(s));
    }
}

// === kBC: block 0 = chain -> flag; blocks 1..147 = D2 prefetch -> wait -> out ===
__global__ void __launch_bounds__(NT) kBC_chain_out(
    const float* __restrict__ PE,  const float* __restrict__ D1w,
    const float* __restrict__ Attw, const float* __restrict__ D2w,
    float* __restrict__ out)
{
    __shared__ float sc0[512], sc1[512], sp0[4096], sp1[4096];
    __shared__ float sw[Dc], red[NT];
    const int t = threadIdx.x, b = blockIdx.x;

    if (b == 0) {
        // ---------------- serial chain ----------------
        const float inv1 = 1.0f / (float)(Lc - 1);
        const float inv2 = 1.0f / (float)Lc;
        const int col = t & 255, q = t >> 8;

        // p-reduce over 148 block-partials (4-way split) + PE bias
        {
            float r0s = 0.f, r1s = 0.f;
            #pragma unroll 4
            for (int i = q; i < NB; i += 4) {
                r0s += g_part[0][i][col];
                r1s += g_part[1][i][col];
            }
            sp0[q * 256 + col] = r0s;
            sp1[q * 256 + col] = r1s;
            __syncthreads();
            if (t < 256) {
                float p0 = PE[(size_t)(Lc - 2) * Dc + t]
                         + sp0[t] + sp0[256 + t] + sp0[512 + t] + sp0[768 + t];
                float p1 = PE[(size_t)(Lc - 1) * Dc + t]
                         + sp1[t] + sp1[256 + t] + sp1[512 + t] + sp1[768 + t];
                sc0[t] = p0;  sc0[Dc + t] = (p0 + p1) * inv1;   // pool1 rows
                sc1[t] = p1;  sc1[Dc + t] = p1 * inv2;
            }
            __syncthreads();
        }

        const int kk = t >> 6;    // 16-way k-split over the 512 concat dim
        const int cg = t & 63;    // 4 columns each
        float d0f = 0.f, d1f = 0.f;

        // dense1 = concat(p, pool1) @ D1
        {
            float d00=0,d01=0,d02=0,d03=0, d10=0,d11=0,d12=0,d13=0;
            #pragma unroll 8
            for (int k = kk; k < 2 * Dc; k += 16) {
                float4 v = *(const float4*)(D1w + (size_t)k * Dc + cg * 4);
                float c0 = sc0[k], c1 = sc1[k];
                d00 = fmaf(c0, v.x, d00); d01 = fmaf(c0, v.y, d01);
                d02 = fmaf(c0, v.z, d02); d03 = fmaf(c0, v.w, d03);
                d10 = fmaf(c1, v.x, d10); d11 = fmaf(c1, v.y, d11);
                d12 = fmaf(c1, v.z, d12); d13 = fmaf(c1, v.w, d13);
            }
            const int o = kk * 256 + cg * 4;
            sp0[o+0]=d00; sp0[o+1]=d01; sp0[o+2]=d02; sp0[o+3]=d03;
            sp1[o+0]=d10; sp1[o+1]=d11; sp1[o+2]=d12; sp1[o+3]=d13;
            __syncthreads();
            if (t < 256) {
                #pragma unroll
                for (int j = 0; j < 16; ++j) { d0f += sp0[j*256+t]; d1f += sp1[j*256+t]; }
                sc0[t] = d0f;  sc0[Dc + t] = (d0f + d1f) * inv1;  // pool2 rows
                sc1[t] = d1f;  sc1[Dc + t] = d1f * inv2;
            }
            __syncthreads();
        }

        // attention = concat(dense1, pool2) @ Att; w = d0*a0 + d1*a1
        {
            float a00=0,a01=0,a02=0,a03=0, a10=0,a11=0,a12=0,a13=0;
            #pragma unroll 8
            for (int k = kk; k < 2 * Dc; k += 16) {
                float4 v = *(const float4*)(Attw + (size_t)k * Dc + cg * 4);
                float c0 = sc0[k], c1 = sc1[k];
                a00 = fmaf(c0, v.x, a00); a01 = fmaf(c0, v.y, a01);
                a02 = fmaf(c0, v.z, a02); a03 = fmaf(c0, v.w, a03);
                a10 = fmaf(c1, v.x, a10); a11 = fmaf(c1, v.y, a11);
                a12 = fmaf(c1, v.z, a12); a13 = fmaf(c1, v.w, a13);
            }
            const int o = kk * 256 + cg * 4;
            sp0[o+0]=a00; sp0[o+1]=a01; sp0[o+2]=a02; sp0[o+3]=a03;
            sp1[o+0]=a10; sp1[o+1]=a11; sp1[o+2]=a12; sp1[o+3]=a13;
            __syncthreads();
            if (t < 256) {
                float a0f = 0.f, a1f = 0.f;
                #pragma unroll
                for (int j = 0; j < 16; ++j) { a0f += sp0[j*256+t]; a1f += sp1[j*256+t]; }
                g_w[t] = d0f * a0f + d1f * a1f;  // SA.T sum of the 2 surviving rows
            }
            __syncthreads();
        }
        if (t == 0) {
            __threadfence();     // publish g_w
            g_flag = 1;          // one-way release; waiters proceed
        }
    } else {
        // ---- blocks 1..147: stream D2 (32.8 MB) into L2 behind the chain ----
        const float4* d2v = (const float4*)D2w;
        const int total = (Dc * Ic) / 4;     // 2,048,000 float4
        float s = 0.f;
        #pragma unroll 4
        for (int idx = (b - 1) * NT + t; idx < total; idx += (NB - 1) * NT) {
            float4 v = __ldcg(d2v + idx);
            s += v.x + v.y + v.z + v.w;
        }
        asm volatile("" :: "f"(s));

        // one-way wait for g_w (block 0 is co-resident: grid == SM count)
        if (t == 0) {
            while (g_flag == 0) { }
            __threadfence();     // acquire
        }
        __syncthreads();
    }

    // ---------------- out = w @ D2 (mostly L2-resident) ----------------
    if (t < Dc) sw[t] = g_w[t];
    __syncthreads();
    const int c  = t & 127;      // output column within chunk
    const int dg = t >> 7;       // 0..7, 32 d's each
    for (int ch = b; ch < NCHUNK_C; ch += NB) {
        const int i = ch * 128 + c;
        const float* d2  = D2w + (size_t)(dg * 32) * Ic + i;
        const float* swq = sw + dg * 32;
        float acc = 0.f;
        #pragma unroll
        for (int d = 0; d < 32; ++d)
            acc = fmaf(swq[d], d2[(size_t)d * Ic], acc);
        red[dg * 128 + c] = acc;
        __syncthreads();
        if (t < 128) {
            float s = 0.f;
            #pragma unroll
            for (int j = 0; j < 8; ++j) s += red[j * 128 + t];
            out[ch * 128 + t] = s;
        }
        __syncthreads();
    }
}

extern "C" void kernel_launch(void* const* d_in, const int* in_sizes, int n_in,
                              void* d_out, int out_size) {
    const float* x   = (const float*)d_in[0];  // [L, I]
    const float* DE  = (const float*)d_in[1];  // [I, D]
    const float* PE  = (const float*)d_in[2];  // [L, D]
    const float* D1w = (const float*)d_in[3];  // [2D, D]
    const float* D2w = (const float*)d_in[4];  // [D, I]
    const float* Att = (const float*)d_in[5];  // [2D, D]
    float* out = (float*)d_out;                // [1, I]
    (void)in_sizes; (void)n_in; (void)out_size;

    kA_posembed<<<NB, NT>>>(x, DE, D1w, Att);
    kBC_chain_out<<<NB, NT>>>(PE, D1w, Att, D2w, out);
}